// round 8
// baseline (speedup 1.0000x reference)
#include <cuda_runtime.h>
#include <math.h>
#include <stdint.h>

#define BATCH 8192
#define KOBJ  6
#define VD    2048
#define QD    1024
#define NH    1024
#define NROWS (BATCH*KOBJ)
#define LDW   (VD+QD)          // 3072, W1 row stride

// GEMM tiling: CTA 256x256x32, 16 warps (4m x 4n), warp tile 64x64
#define THREADS 512
#define BM 256
#define BN 256
#define BK 32
#define PAD 36                  // u32 pitch
#define A_U32 (BM*PAD)
#define B_U32 (BN*PAD)
#define STG_U32 (A_U32+B_U32)
#define SMEM_DYN (2*STG_U32*4)  // 147456 B

__device__ float g_W1r[(size_t)NH*LDW];   // rna-rounded W1 (tf32 values in f32)
__device__ float g_P[(size_t)BATCH*NH];   // q-projection + b1
__device__ float g_logits[NROWS];

__device__ __forceinline__ uint32_t f2tf(float x){
    uint32_t r; asm("cvt.rna.tf32.f32 %0, %1;" : "=r"(r) : "f"(x)); return r;
}
__device__ __forceinline__ uint32_t smem_u32(const void* p){
    uint32_t a;
    asm("{ .reg .u64 t; cvta.to.shared.u64 t, %1; cvt.u32.u64 %0, t; }" : "=r"(a) : "l"(p));
    return a;
}
__device__ __forceinline__ void cp16(uint32_t dst, const void* src){
    asm volatile("cp.async.cg.shared.global [%0], [%1], 16;" :: "r"(dst), "l"(src) : "memory");
}
#define CP_COMMIT() asm volatile("cp.async.commit_group;" ::: "memory")
#define CP_WAIT(n)  asm volatile("cp.async.wait_group %0;" :: "n"(n) : "memory")

__global__ void round_W1_kernel(const float* __restrict__ W1){
    size_t i = (size_t)blockIdx.x*blockDim.x + threadIdx.x;
    const float4 f = ((const float4*)W1)[i];
    ((uint4*)g_W1r)[i] = make_uint4(f2tf(f.x), f2tf(f.y), f2tf(f.z), f2tf(f.w));
}
__global__ void zero_logits_kernel(){
    int i = blockIdx.x*blockDim.x + threadIdx.x;
    if (i < NROWS) g_logits[i] = 0.f;
}

// C[m,n] = sum_k A[m,k]*W1r(n,k)
// EPI==0: A=q -> g_P[row,col] = C + bias
// EPI==1: A=v -> logits[row] += sum_col Wl[col]*relu(C + g_P[row/6,col])
template<int EPI>
__global__ void __launch_bounds__(THREADS, 1)
gemm_tc(const float* __restrict__ A,
        const float* __restrict__ bias, const float* __restrict__ Wl)
{
    constexpr int LDA  = (EPI == 0) ? QD : VD;
    constexpr int KDIM = (EPI == 0) ? QD : VD;
    constexpr int KOFF = (EPI == 0) ? VD : 0;
    constexpr int KT   = KDIM / BK;

    extern __shared__ uint32_t sm[];
    uint32_t* bufA[2] = { sm,          sm + STG_U32 };
    uint32_t* bufB[2] = { sm + A_U32,  sm + STG_U32 + A_U32 };

    const int tid  = threadIdx.x;
    const int warp = tid >> 5, lane = tid & 31;
    const int wm = warp & 3, wn = warp >> 2;       // 4m x 4n warp grid
    const int grp = lane >> 2, tig = lane & 3;
    const int m0 = blockIdx.x * BM;
    const int n0 = blockIdx.y * BN;

    const float* Bw = g_W1r + KOFF;    // device-side symbol reference only

    float4 areg[4];

    auto LDGA = [&](int t){
        #pragma unroll
        for (int j = 0; j < 4; j++){
            int u = tid + THREADS*j, r = u >> 3, cc = u & 7;
            areg[j] = __ldg((const float4*)(A + (size_t)(m0+r)*LDA + t*BK + cc*4));
        }
    };
    auto STSA = [&](int b){
        #pragma unroll
        for (int j = 0; j < 4; j++){
            int u = tid + THREADS*j, r = u >> 3, cc = u & 7;
            float4 f = areg[j];
            *(uint4*)(bufA[b] + r*PAD + cc*4) =
                make_uint4(f2tf(f.x), f2tf(f.y), f2tf(f.z), f2tf(f.w));
        }
    };
    auto CPB = [&](int t, int b){
        #pragma unroll
        for (int j = 0; j < 4; j++){
            int u = tid + THREADS*j, r = u >> 3, cc = u & 7;
            cp16(smem_u32(bufB[b] + r*PAD + cc*4),
                 Bw + (size_t)(n0+r)*LDW + t*BK + cc*4);
        }
        CP_COMMIT();
    };

    float c[4][8][4];
    #pragma unroll
    for (int i=0;i<4;i++)
      #pragma unroll
      for (int j=0;j<8;j++){ c[i][j][0]=0.f;c[i][j][1]=0.f;c[i][j][2]=0.f;c[i][j][3]=0.f; }

    // prologue: fill both stages (proven R6 structure)
    CPB(0,0); LDGA(0);
    CPB(1,1);
    STSA(0);
    LDGA(1);
    STSA(1);
    CP_WAIT(1);
    __syncthreads();

    for (int i = 0; i < KT; i++){
        if (i + 2 < KT) LDGA(i+2);

        const uint32_t* Ab = bufA[i & 1];
        const uint32_t* Bb = bufB[i & 1];
        #pragma unroll
        for (int ks = 0; ks < 4; ks++){
            const int kb = ks*8;
            uint32_t af[4][4], bfr[8][2];
            #pragma unroll
            for (int mi = 0; mi < 4; mi++){
                int mr = wm*64 + mi*16 + grp;
                af[mi][0] = Ab[ mr   *PAD + kb + tig    ];
                af[mi][1] = Ab[(mr+8)*PAD + kb + tig    ];
                af[mi][2] = Ab[ mr   *PAD + kb + tig + 4];
                af[mi][3] = Ab[(mr+8)*PAD + kb + tig + 4];
            }
            #pragma unroll
            for (int ni = 0; ni < 8; ni++){
                int nc = wn*64 + ni*8 + grp;
                bfr[ni][0] = Bb[nc*PAD + kb + tig    ];
                bfr[ni][1] = Bb[nc*PAD + kb + tig + 4];
            }
            #pragma unroll
            for (int mi = 0; mi < 4; mi++)
              #pragma unroll
              for (int ni = 0; ni < 8; ni++)
                asm volatile("mma.sync.aligned.m16n8k8.row.col.f32.tf32.tf32.f32 "
                  "{%0,%1,%2,%3}, {%4,%5,%6,%7}, {%8,%9}, {%0,%1,%2,%3};"
                  : "+f"(c[mi][ni][0]), "+f"(c[mi][ni][1]),
                    "+f"(c[mi][ni][2]), "+f"(c[mi][ni][3])
                  : "r"(af[mi][0]), "r"(af[mi][1]), "r"(af[mi][2]), "r"(af[mi][3]),
                    "r"(bfr[ni][0]), "r"(bfr[ni][1]));
        }
        __syncthreads();
        if (i + 2 < KT){
            STSA(i & 1);
            CPB(i+2, i & 1);
            CP_WAIT(1);
        } else {
            CP_WAIT(0);
        }
        __syncthreads();
    }

    if (EPI == 0){
        #pragma unroll
        for (int ni = 0; ni < 8; ni++){
            int col = n0 + wn*64 + ni*8 + tig*2;
            float b0 = bias[col], b1v = bias[col+1];
            #pragma unroll
            for (int mi = 0; mi < 4; mi++){
                int row = m0 + wm*64 + mi*16 + grp;
                g_P[(size_t)row*NH + col    ] = c[mi][ni][0] + b0;
                g_P[(size_t)row*NH + col + 1] = c[mi][ni][1] + b1v;
                g_P[(size_t)(row+8)*NH + col    ] = c[mi][ni][2] + b0;
                g_P[(size_t)(row+8)*NH + col + 1] = c[mi][ni][3] + b1v;
            }
        }
    } else {
        #pragma unroll
        for (int mi = 0; mi < 4; mi++){
            int row = m0 + wm*64 + mi*16 + grp;
            int ba = row / KOBJ, bb = (row + 8) / KOBJ;
            float rs0 = 0.f, rs1 = 0.f;
            #pragma unroll
            for (int ni = 0; ni < 8; ni++){
                int col = n0 + wn*64 + ni*8 + tig*2;
                float wl0 = __ldg(Wl + col), wl1 = __ldg(Wl + col + 1);
                rs0 += fmaxf(c[mi][ni][0] + g_P[(size_t)ba*NH + col    ], 0.f) * wl0
                     + fmaxf(c[mi][ni][1] + g_P[(size_t)ba*NH + col + 1], 0.f) * wl1;
                rs1 += fmaxf(c[mi][ni][2] + g_P[(size_t)bb*NH + col    ], 0.f) * wl0
                     + fmaxf(c[mi][ni][3] + g_P[(size_t)bb*NH + col + 1], 0.f) * wl1;
            }
            rs0 += __shfl_xor_sync(0xffffffffu, rs0, 1);
            rs0 += __shfl_xor_sync(0xffffffffu, rs0, 2);
            rs1 += __shfl_xor_sync(0xffffffffu, rs1, 1);
            rs1 += __shfl_xor_sync(0xffffffffu, rs1, 2);
            if (tig == 0){
                atomicAdd(&g_logits[row],     rs0);
                atomicAdd(&g_logits[row + 8], rs1);
            }
        }
    }
}

__global__ void __launch_bounds__(256) final_kernel(
    const float* __restrict__ mask, const float* __restrict__ bl,
    const float* __restrict__ Wse1, const float* __restrict__ Wse2,
    const float* __restrict__ Wf,   const float* __restrict__ bf,
    float* __restrict__ out)
{
    int b = blockIdx.x, tid = threadIdx.x;
    __shared__ float  s_l[KOBJ], s_s[KOBJ];
    __shared__ float4 s_wf[VD/4], s_bf[VD/4];
    for (int d = tid; d < VD/4; d += 256){
        s_wf[d] = ((const float4*)Wf)[d];
        s_bf[d] = ((const float4*)bf)[d];
    }
    if (tid < KOBJ) s_l[tid] = g_logits[b*KOBJ + tid] + bl[0];
    __syncthreads();
    if (tid < KOBJ){
        float l = s_l[tid];
        float mx = s_l[0];
        #pragma unroll
        for (int k=1;k<KOBJ;k++) mx = fmaxf(mx, s_l[k]);
        float sum = 0.f;
        #pragma unroll
        for (int k=0;k<KOBJ;k++) sum += expf(s_l[k]-mx);
        out[b*KOBJ + tid] = expf(l-mx)/sum;
        float total = 0.f;
        #pragma unroll
        for (int k=0;k<KOBJ;k++) total += s_l[k]*mask[b*KOBJ+k];
        float x = total - l*mask[b*KOBJ+tid];
        float acc = 0.f;
        for (int i=0;i<128;i++) acc += Wse2[i]*fmaxf(x*Wse1[i], 0.f);
        float y = 1.f/(1.f + expf(-acc));
        s_s[tid] = x*(1.f-y) + l;
    }
    __syncthreads();
    float* out2 = out + NROWS;
    #pragma unroll
    for (int k=0;k<KOBJ;k++){
        float s = s_s[k];
        float4* o = (float4*)(out2 + (size_t)(b*KOBJ+k)*VD);
        for (int d = tid; d < VD/4; d += 256){
            float4 wf = s_wf[d], bv = s_bf[d];
            o[d] = make_float4(fmaf(s,wf.x,bv.x), fmaf(s,wf.y,bv.y),
                               fmaf(s,wf.z,bv.z), fmaf(s,wf.w,bv.w));
        }
    }
}

extern "C" void kernel_launch(void* const* d_in, const int* in_sizes, int n_in,
                              void* d_out, int out_size)
{
    const float* v    = (const float*)d_in[0];
    const float* q    = (const float*)d_in[1];
    const float* mask = (const float*)d_in[2];
    const float* W1   = (const float*)d_in[3];
    const float* b1   = (const float*)d_in[4];
    const float* Wl   = (const float*)d_in[5];
    const float* bl   = (const float*)d_in[6];
    const float* Wse1 = (const float*)d_in[7];
    const float* Wse2 = (const float*)d_in[8];
    const float* Wf   = (const float*)d_in[9];
    const float* bf   = (const float*)d_in[10];
    float* out = (float*)d_out;

    cudaFuncSetAttribute(gemm_tc<0>, cudaFuncAttributeMaxDynamicSharedMemorySize, SMEM_DYN);
    cudaFuncSetAttribute(gemm_tc<1>, cudaFuncAttributeMaxDynamicSharedMemorySize, SMEM_DYN);

    zero_logits_kernel<<<(NROWS+255)/256, 256>>>();
    round_W1_kernel<<<(NH*LDW/4)/256, 256>>>(W1);
    // Stage A: g_P[b,h] = q[b]·W1q[h] + b1[h]
    gemm_tc<0><<<dim3(BATCH/BM, NH/BN), THREADS, SMEM_DYN>>>(q, b1, nullptr);
    // Stage B: logits[row] += Σ_h Wl[h]·relu(v[row]·W1v[h] + g_P[row/6,h])
    gemm_tc<1><<<dim3(NROWS/BM, NH/BN), THREADS, SMEM_DYN>>>(v, nullptr, Wl);
    // Stage C
    final_kernel<<<BATCH, 256>>>(mask, bl, Wse1, Wse2, Wf, bf, out);
}

// round 10
// speedup vs baseline: 3.5977x; 3.5977x over previous
#include <cuda_runtime.h>
#include <math.h>
#include <stdint.h>

#define BATCH 8192
#define KOBJ  6
#define VD    2048
#define QD    1024
#define NH    1024
#define NROWS (BATCH*KOBJ)
#define LDW   (VD+QD)          // 3072, W1 row stride

// GEMM tiling: CTA 128x256x32, 8 warps (2m x 4n), warp tile 64x64  (R6 proven)
#define THREADS 256
#define BM 128
#define BN 256
#define BK 32
#define PAD 36                  // u32 pitch; row stride 144B (16B aligned for ldmatrix)
#define A_U32 (BM*PAD)
#define B_U32 (BN*PAD)
#define STG_U32 (A_U32+B_U32)
#define SMEM_DYN (2*STG_U32*4)  // 110592 B

__device__ float g_W1r[(size_t)NH*LDW];   // rna-rounded W1 (tf32 values in f32)
__device__ float g_P[(size_t)BATCH*NH];   // q-projection + b1
__device__ float g_logits[NROWS];

__device__ __forceinline__ uint32_t f2tf(float x){
    uint32_t r; asm("cvt.rna.tf32.f32 %0, %1;" : "=r"(r) : "f"(x)); return r;
}
__device__ __forceinline__ uint32_t smem_u32(const void* p){
    uint32_t a;
    asm("{ .reg .u64 t; cvta.to.shared.u64 t, %1; cvt.u32.u64 %0, t; }" : "=r"(a) : "l"(p));
    return a;
}
__device__ __forceinline__ void cp16(uint32_t dst, const void* src){
    asm volatile("cp.async.cg.shared.global [%0], [%1], 16;" :: "r"(dst), "l"(src) : "memory");
}
#define CP_COMMIT() asm volatile("cp.async.commit_group;" ::: "memory")
#define CP_WAIT(n)  asm volatile("cp.async.wait_group %0;" :: "n"(n) : "memory")

__device__ __forceinline__ void ldsm_x4(uint32_t &r0, uint32_t &r1, uint32_t &r2, uint32_t &r3,
                                        uint32_t addr){
    asm volatile("ldmatrix.sync.aligned.m8n8.x4.shared.b16 {%0,%1,%2,%3}, [%4];"
        : "=r"(r0), "=r"(r1), "=r"(r2), "=r"(r3) : "r"(addr));
}

__global__ void round_W1_kernel(const float* __restrict__ W1){
    size_t i = (size_t)blockIdx.x*blockDim.x + threadIdx.x;
    const float4 f = ((const float4*)W1)[i];
    ((uint4*)g_W1r)[i] = make_uint4(f2tf(f.x), f2tf(f.y), f2tf(f.z), f2tf(f.w));
}
__global__ void zero_logits_kernel(){
    int i = blockIdx.x*blockDim.x + threadIdx.x;
    if (i < NROWS) g_logits[i] = 0.f;
}

// C[m,n] = sum_k A[m,k]*W1r(n,k)
// EPI==0: A=q -> g_P[row,col] = C + bias
// EPI==1: A=v -> logits[row] += sum_col Wl[col]*relu(C + g_P[row/6,col])
template<int EPI>
__global__ void __launch_bounds__(THREADS, 1)
gemm_tc(const float* __restrict__ A,
        const float* __restrict__ bias, const float* __restrict__ Wl)
{
    constexpr int LDA  = (EPI == 0) ? QD : VD;
    constexpr int KDIM = (EPI == 0) ? QD : VD;
    constexpr int KOFF = (EPI == 0) ? VD : 0;
    constexpr int KT   = KDIM / BK;

    extern __shared__ uint32_t sm[];
    uint32_t* bufA[2] = { sm,          sm + STG_U32 };
    uint32_t* bufB[2] = { sm + A_U32,  sm + STG_U32 + A_U32 };

    const int tid  = threadIdx.x;
    const int warp = tid >> 5, lane = tid & 31;
    const int wm = warp & 1, wn = warp >> 1;      // 2m x 4n warp grid
    const int grp = lane >> 2, tig = lane & 3;
    const int m0 = blockIdx.x * BM;
    const int n0 = blockIdx.y * BN;

    const float* Bw = g_W1r + KOFF;    // device-side symbol reference only

    // ldmatrix per-lane address components (u32-index units)
    const int aRow  = ((lane >> 3) & 1) * 8 + (lane & 7);
    const int aCol  = (lane >> 4) * 4;
    const int aIdx0 = (wm*64 + aRow) * PAD + aCol;        // + mi*16*PAD + kb
    const int bRow  = lane & 7;
    const int bNi   = ((lane >> 4) & 1) * 8;
    const int bCol  = ((lane >> 3) & 1) * 4;
    const int bIdx0 = (wn*64 + bNi + bRow) * PAD + bCol;  // + ni2*16*PAD + kb

    const uint32_t smA[2] = { smem_u32(bufA[0]), smem_u32(bufA[1]) };
    const uint32_t smB[2] = { smem_u32(bufB[0]), smem_u32(bufB[1]) };

    float4 areg[4];

    auto LDGA = [&](int t){
        #pragma unroll
        for (int j = 0; j < 4; j++){                       // 256 thr x 4 = full 128x32 tile
            int u = tid + THREADS*j, r = u >> 3, cc = u & 7;
            areg[j] = __ldg((const float4*)(A + (size_t)(m0+r)*LDA + t*BK + cc*4));
        }
    };
    auto STSA = [&](int b){
        #pragma unroll
        for (int j = 0; j < 4; j++){
            int u = tid + THREADS*j, r = u >> 3, cc = u & 7;
            float4 f = areg[j];
            *(uint4*)(bufA[b] + r*PAD + cc*4) =
                make_uint4(f2tf(f.x), f2tf(f.y), f2tf(f.z), f2tf(f.w));
        }
    };
    auto CPB = [&](int t, int b){
        #pragma unroll
        for (int j = 0; j < 8; j++){
            int u = tid + THREADS*j, r = u >> 3, cc = u & 7;
            cp16(smem_u32(bufB[b] + r*PAD + cc*4),
                 Bw + (size_t)(n0+r)*LDW + t*BK + cc*4);
        }
        CP_COMMIT();
    };

    float c[4][8][4];
    #pragma unroll
    for (int i=0;i<4;i++)
      #pragma unroll
      for (int j=0;j<8;j++){ c[i][j][0]=0.f;c[i][j][1]=0.f;c[i][j][2]=0.f;c[i][j][3]=0.f; }

    // prologue: fill both stages (R6 proven structure)
    CPB(0,0); LDGA(0);
    CPB(1,1);
    STSA(0);
    LDGA(1);
    STSA(1);
    CP_WAIT(1);
    __syncthreads();

    for (int i = 0; i < KT; i++){
        if (i + 2 < KT) LDGA(i+2);

        const uint32_t sA = smA[i & 1];
        const uint32_t sB = smB[i & 1];
        #pragma unroll
        for (int ks = 0; ks < 4; ks++){
            const int kb = ks*8;
            uint32_t af[4][4], bfr[8][2];
            #pragma unroll
            for (int mi = 0; mi < 4; mi++)
                ldsm_x4(af[mi][0], af[mi][1], af[mi][2], af[mi][3],
                        sA + (uint32_t)(aIdx0 + mi*16*PAD + kb)*4u);
            #pragma unroll
            for (int ni2 = 0; ni2 < 4; ni2++)
                ldsm_x4(bfr[2*ni2][0], bfr[2*ni2][1], bfr[2*ni2+1][0], bfr[2*ni2+1][1],
                        sB + (uint32_t)(bIdx0 + ni2*16*PAD + kb)*4u);
            #pragma unroll
            for (int mi = 0; mi < 4; mi++)
              #pragma unroll
              for (int ni = 0; ni < 8; ni++)
                asm volatile("mma.sync.aligned.m16n8k8.row.col.f32.tf32.tf32.f32 "
                  "{%0,%1,%2,%3}, {%4,%5,%6,%7}, {%8,%9}, {%0,%1,%2,%3};"
                  : "+f"(c[mi][ni][0]), "+f"(c[mi][ni][1]),
                    "+f"(c[mi][ni][2]), "+f"(c[mi][ni][3])
                  : "r"(af[mi][0]), "r"(af[mi][1]), "r"(af[mi][2]), "r"(af[mi][3]),
                    "r"(bfr[ni][0]), "r"(bfr[ni][1]));
        }
        __syncthreads();
        if (i + 2 < KT){
            STSA(i & 1);
            CPB(i+2, i & 1);
            CP_WAIT(1);
        } else {
            CP_WAIT(0);
        }
        __syncthreads();
    }

    if (EPI == 0){
        #pragma unroll
        for (int ni = 0; ni < 8; ni++){
            int col = n0 + wn*64 + ni*8 + tig*2;
            float b0 = bias[col], b1v = bias[col+1];
            #pragma unroll
            for (int mi = 0; mi < 4; mi++){
                int row = m0 + wm*64 + mi*16 + grp;
                g_P[(size_t)row*NH + col    ] = c[mi][ni][0] + b0;
                g_P[(size_t)row*NH + col + 1] = c[mi][ni][1] + b1v;
                g_P[(size_t)(row+8)*NH + col    ] = c[mi][ni][2] + b0;
                g_P[(size_t)(row+8)*NH + col + 1] = c[mi][ni][3] + b1v;
            }
        }
    } else {
        #pragma unroll
        for (int mi = 0; mi < 4; mi++){
            int row = m0 + wm*64 + mi*16 + grp;
            int ba = row / KOBJ, bb = (row + 8) / KOBJ;
            float rs0 = 0.f, rs1 = 0.f;
            #pragma unroll
            for (int ni = 0; ni < 8; ni++){
                int col = n0 + wn*64 + ni*8 + tig*2;
                float wl0 = __ldg(Wl + col), wl1 = __ldg(Wl + col + 1);
                rs0 += fmaxf(c[mi][ni][0] + g_P[(size_t)ba*NH + col    ], 0.f) * wl0
                     + fmaxf(c[mi][ni][1] + g_P[(size_t)ba*NH + col + 1], 0.f) * wl1;
                rs1 += fmaxf(c[mi][ni][2] + g_P[(size_t)bb*NH + col    ], 0.f) * wl0
                     + fmaxf(c[mi][ni][3] + g_P[(size_t)bb*NH + col + 1], 0.f) * wl1;
            }
            rs0 += __shfl_xor_sync(0xffffffffu, rs0, 1);
            rs0 += __shfl_xor_sync(0xffffffffu, rs0, 2);
            rs1 += __shfl_xor_sync(0xffffffffu, rs1, 1);
            rs1 += __shfl_xor_sync(0xffffffffu, rs1, 2);
            if (tig == 0){
                atomicAdd(&g_logits[row],     rs0);
                atomicAdd(&g_logits[row + 8], rs1);
            }
        }
    }
}

__global__ void __launch_bounds__(256) final_kernel(
    const float* __restrict__ mask, const float* __restrict__ bl,
    const float* __restrict__ Wse1, const float* __restrict__ Wse2,
    const float* __restrict__ Wf,   const float* __restrict__ bf,
    float* __restrict__ out)
{
    int b = blockIdx.x, tid = threadIdx.x;
    __shared__ float  s_l[KOBJ], s_s[KOBJ];
    __shared__ float4 s_wf[VD/4], s_bf[VD/4];
    for (int d = tid; d < VD/4; d += 256){
        s_wf[d] = ((const float4*)Wf)[d];
        s_bf[d] = ((const float4*)bf)[d];
    }
    if (tid < KOBJ) s_l[tid] = g_logits[b*KOBJ + tid] + bl[0];
    __syncthreads();
    if (tid < KOBJ){
        float l = s_l[tid];
        float mx = s_l[0];
        #pragma unroll
        for (int k=1;k<KOBJ;k++) mx = fmaxf(mx, s_l[k]);
        float sum = 0.f;
        #pragma unroll
        for (int k=0;k<KOBJ;k++) sum += expf(s_l[k]-mx);
        out[b*KOBJ + tid] = expf(l-mx)/sum;
        float total = 0.f;
        #pragma unroll
        for (int k=0;k<KOBJ;k++) total += s_l[k]*mask[b*KOBJ+k];
        float x = total - l*mask[b*KOBJ+tid];
        float acc = 0.f;
        for (int i=0;i<128;i++) acc += Wse2[i]*fmaxf(x*Wse1[i], 0.f);
        float y = 1.f/(1.f + expf(-acc));
        s_s[tid] = x*(1.f-y) + l;
    }
    __syncthreads();
    float* out2 = out + NROWS;
    #pragma unroll
    for (int k=0;k<KOBJ;k++){
        float s = s_s[k];
        float4* o = (float4*)(out2 + (size_t)(b*KOBJ+k)*VD);
        for (int d = tid; d < VD/4; d += 256){
            float4 wf = s_wf[d], bv = s_bf[d];
            o[d] = make_float4(fmaf(s,wf.x,bv.x), fmaf(s,wf.y,bv.y),
                               fmaf(s,wf.z,bv.z), fmaf(s,wf.w,bv.w));
        }
    }
}

extern "C" void kernel_launch(void* const* d_in, const int* in_sizes, int n_in,
                              void* d_out, int out_size)
{
    const float* v    = (const float*)d_in[0];
    const float* q    = (const float*)d_in[1];
    const float* mask = (const float*)d_in[2];
    const float* W1   = (const float*)d_in[3];
    const float* b1   = (const float*)d_in[4];
    const float* Wl   = (const float*)d_in[5];
    const float* bl   = (const float*)d_in[6];
    const float* Wse1 = (const float*)d_in[7];
    const float* Wse2 = (const float*)d_in[8];
    const float* Wf   = (const float*)d_in[9];
    const float* bf   = (const float*)d_in[10];
    float* out = (float*)d_out;

    cudaFuncSetAttribute(gemm_tc<0>, cudaFuncAttributeMaxDynamicSharedMemorySize, SMEM_DYN);
    cudaFuncSetAttribute(gemm_tc<1>, cudaFuncAttributeMaxDynamicSharedMemorySize, SMEM_DYN);

    zero_logits_kernel<<<(NROWS+255)/256, 256>>>();
    round_W1_kernel<<<(NH*LDW/4)/256, 256>>>(W1);
    // Stage A: g_P[b,h] = q[b]·W1q[h] + b1[h]
    gemm_tc<0><<<dim3(BATCH/BM, NH/BN), THREADS, SMEM_DYN>>>(q, b1, nullptr);
    // Stage B: logits[row] += Σ_h Wl[h]·relu(v[row]·W1v[h] + g_P[row/6,h])
    gemm_tc<1><<<dim3(NROWS/BM, NH/BN), THREADS, SMEM_DYN>>>(v, nullptr, Wl);
    // Stage C
    final_kernel<<<BATCH, 256>>>(mask, bl, Wse1, Wse2, Wf, bf, out);
}

// round 11
// speedup vs baseline: 3.6036x; 1.0016x over previous
#include <cuda_runtime.h>
#include <math.h>
#include <stdint.h>

#define BATCH 8192
#define KOBJ  6
#define VD    2048
#define QD    1024
#define NH    1024
#define NROWS (BATCH*KOBJ)
#define LDW   (VD+QD)          // 3072, W1 row stride

// GEMM tiling: CTA 128x256x32, 8 warps (2m x 4n), warp tile 64x64
#define THREADS 256
#define BM 128
#define BN 256
#define BK 32
#define PAD 36                  // u32 pitch; row stride 144B (16B aligned for ldmatrix)
#define A_U32 (BM*PAD)
#define B_U32 (BN*PAD)
#define STG_U32 (A_U32+B_U32)
#define SMEM_DYN (2*STG_U32*4)  // 110592 B

__device__ float g_W1r[(size_t)NH*LDW];   // rna-rounded W1 (tf32 values in f32)
__device__ float g_P[(size_t)BATCH*NH];   // q-projection + b1
__device__ float g_logits[NROWS];

__device__ __forceinline__ uint32_t f2tf(float x){
    uint32_t r; asm("cvt.rna.tf32.f32 %0, %1;" : "=r"(r) : "f"(x)); return r;
}
__device__ __forceinline__ uint32_t smem_u32(const void* p){
    uint32_t a;
    asm("{ .reg .u64 t; cvta.to.shared.u64 t, %1; cvt.u32.u64 %0, t; }" : "=r"(a) : "l"(p));
    return a;
}
__device__ __forceinline__ void cp16(uint32_t dst, const void* src){
    asm volatile("cp.async.cg.shared.global [%0], [%1], 16;" :: "r"(dst), "l"(src) : "memory");
}
#define CP_COMMIT() asm volatile("cp.async.commit_group;" ::: "memory")
#define CP_WAIT(n)  asm volatile("cp.async.wait_group %0;" :: "n"(n) : "memory")

__device__ __forceinline__ void ldsm_x4(uint32_t &r0, uint32_t &r1, uint32_t &r2, uint32_t &r3,
                                        uint32_t addr){
    asm volatile("ldmatrix.sync.aligned.m8n8.x4.shared.b16 {%0,%1,%2,%3}, [%4];"
        : "=r"(r0), "=r"(r1), "=r"(r2), "=r"(r3) : "r"(addr));
}

__global__ void round_W1_kernel(const float* __restrict__ W1){
    size_t i = (size_t)blockIdx.x*blockDim.x + threadIdx.x;
    const float4 f = ((const float4*)W1)[i];
    ((uint4*)g_W1r)[i] = make_uint4(f2tf(f.x), f2tf(f.y), f2tf(f.z), f2tf(f.w));
}
__global__ void zero_logits_kernel(){
    int i = blockIdx.x*blockDim.x + threadIdx.x;
    if (i < NROWS) g_logits[i] = 0.f;
}

// C[m,n] = sum_k A[m,k]*W1r(n,k)
// EPI==0: A=q -> g_P[row,col] = C + bias
// EPI==1: A=v -> logits[row] += sum_col Wl[col]*relu(C + g_P[row/6,col])
template<int EPI>
__global__ void __launch_bounds__(THREADS, 1)
gemm_tc(const float* __restrict__ A,
        const float* __restrict__ bias, const float* __restrict__ Wl)
{
    constexpr int LDA  = (EPI == 0) ? QD : VD;
    constexpr int KDIM = (EPI == 0) ? QD : VD;
    constexpr int KOFF = (EPI == 0) ? VD : 0;
    constexpr int KT   = KDIM / BK;

    extern __shared__ uint32_t sm[];
    uint32_t* bufA[2] = { sm,          sm + STG_U32 };
    uint32_t* bufB[2] = { sm + A_U32,  sm + STG_U32 + A_U32 };

    const int tid  = threadIdx.x;
    const int warp = tid >> 5, lane = tid & 31;
    const int wm = warp & 1, wn = warp >> 1;      // 2m x 4n warp grid
    const int grp = lane >> 2, tig = lane & 3;
    const int m0 = blockIdx.x * BM;
    const int n0 = blockIdx.y * BN;

    const float* Bw = g_W1r + KOFF;    // device-side symbol reference only

    // ldmatrix per-lane address components (u32-index units)
    const int aRow  = ((lane >> 3) & 1) * 8 + (lane & 7);
    const int aCol  = (lane >> 4) * 4;
    const int aIdx0 = (wm*64 + aRow) * PAD + aCol;        // + mi*16*PAD + kb
    const int bRow  = lane & 7;
    const int bNi   = ((lane >> 4) & 1) * 8;
    const int bCol  = ((lane >> 3) & 1) * 4;
    const int bIdx0 = (wn*64 + bNi + bRow) * PAD + bCol;  // + ni2*16*PAD + kb

    const uint32_t smA[2] = { smem_u32(bufA[0]), smem_u32(bufA[1]) };
    const uint32_t smB[2] = { smem_u32(bufB[0]), smem_u32(bufB[1]) };

    float4 areg[4];

    auto LDGA = [&](int t){
        #pragma unroll
        for (int j = 0; j < 4; j++){
            int u = tid + THREADS*j, r = u >> 3, cc = u & 7;
            areg[j] = __ldg((const float4*)(A + (size_t)(m0+r)*LDA + t*BK + cc*4));
        }
    };
    auto STSA = [&](int b){
        #pragma unroll
        for (int j = 0; j < 4; j++){
            int u = tid + THREADS*j, r = u >> 3, cc = u & 7;
            float4 f = areg[j];
            *(uint4*)(bufA[b] + r*PAD + cc*4) =
                make_uint4(f2tf(f.x), f2tf(f.y), f2tf(f.z), f2tf(f.w));
        }
    };
    auto CPB = [&](int t, int b){
        #pragma unroll
        for (int j = 0; j < 8; j++){
            int u = tid + THREADS*j, r = u >> 3, cc = u & 7;
            cp16(smem_u32(bufB[b] + r*PAD + cc*4),
                 Bw + (size_t)(n0+r)*LDW + t*BK + cc*4);
        }
        CP_COMMIT();
    };

    float c[4][8][4];
    #pragma unroll
    for (int i=0;i<4;i++)
      #pragma unroll
      for (int j=0;j<8;j++){ c[i][j][0]=0.f;c[i][j][1]=0.f;c[i][j][2]=0.f;c[i][j][3]=0.f; }

    // prologue: fill both stages (R6 proven structure)
    CPB(0,0); LDGA(0);
    CPB(1,1);
    STSA(0);
    LDGA(1);
    STSA(1);
    CP_WAIT(1);
    __syncthreads();

    for (int i = 0; i < KT; i++){
        if (i + 2 < KT) LDGA(i+2);

        const uint32_t sA = smA[i & 1];
        const uint32_t sB = smB[i & 1];

        uint32_t af[4][4], bfr[2][8][2];
        // preload B fragments for ks=0
        #pragma unroll
        for (int ni2 = 0; ni2 < 4; ni2++)
            ldsm_x4(bfr[0][2*ni2][0], bfr[0][2*ni2][1], bfr[0][2*ni2+1][0], bfr[0][2*ni2+1][1],
                    sB + (uint32_t)(bIdx0 + ni2*16*PAD)*4u);

        #pragma unroll
        for (int ks = 0; ks < 4; ks++){
            const int kb = ks*8;
            // A fragments for this ks
            #pragma unroll
            for (int mi = 0; mi < 4; mi++)
                ldsm_x4(af[mi][0], af[mi][1], af[mi][2], af[mi][3],
                        sA + (uint32_t)(aIdx0 + mi*16*PAD + kb)*4u);
            // prefetch B fragments for ks+1 (hides LDS latency behind the MMA burst)
            if (ks < 3){
                #pragma unroll
                for (int ni2 = 0; ni2 < 4; ni2++)
                    ldsm_x4(bfr[(ks+1)&1][2*ni2][0], bfr[(ks+1)&1][2*ni2][1],
                            bfr[(ks+1)&1][2*ni2+1][0], bfr[(ks+1)&1][2*ni2+1][1],
                            sB + (uint32_t)(bIdx0 + ni2*16*PAD + kb + 8)*4u);
            }
            #pragma unroll
            for (int mi = 0; mi < 4; mi++)
              #pragma unroll
              for (int ni = 0; ni < 8; ni++)
                asm volatile("mma.sync.aligned.m16n8k8.row.col.f32.tf32.tf32.f32 "
                  "{%0,%1,%2,%3}, {%4,%5,%6,%7}, {%8,%9}, {%0,%1,%2,%3};"
                  : "+f"(c[mi][ni][0]), "+f"(c[mi][ni][1]),
                    "+f"(c[mi][ni][2]), "+f"(c[mi][ni][3])
                  : "r"(af[mi][0]), "r"(af[mi][1]), "r"(af[mi][2]), "r"(af[mi][3]),
                    "r"(bfr[ks&1][ni][0]), "r"(bfr[ks&1][ni][1]));
        }
        __syncthreads();
        if (i + 2 < KT){
            STSA(i & 1);
            CPB(i+2, i & 1);
            CP_WAIT(1);
        } else {
            CP_WAIT(0);
        }
        __syncthreads();
    }

    if (EPI == 0){
        #pragma unroll
        for (int ni = 0; ni < 8; ni++){
            int col = n0 + wn*64 + ni*8 + tig*2;
            float b0 = bias[col], b1v = bias[col+1];
            #pragma unroll
            for (int mi = 0; mi < 4; mi++){
                int row = m0 + wm*64 + mi*16 + grp;
                g_P[(size_t)row*NH + col    ] = c[mi][ni][0] + b0;
                g_P[(size_t)row*NH + col + 1] = c[mi][ni][1] + b1v;
                g_P[(size_t)(row+8)*NH + col    ] = c[mi][ni][2] + b0;
                g_P[(size_t)(row+8)*NH + col + 1] = c[mi][ni][3] + b1v;
            }
        }
    } else {
        #pragma unroll
        for (int mi = 0; mi < 4; mi++){
            int row = m0 + wm*64 + mi*16 + grp;
            int ba = row / KOBJ, bb = (row + 8) / KOBJ;
            float rs0 = 0.f, rs1 = 0.f;
            #pragma unroll
            for (int ni = 0; ni < 8; ni++){
                int col = n0 + wn*64 + ni*8 + tig*2;
                float wl0 = __ldg(Wl + col), wl1 = __ldg(Wl + col + 1);
                rs0 += fmaxf(c[mi][ni][0] + g_P[(size_t)ba*NH + col    ], 0.f) * wl0
                     + fmaxf(c[mi][ni][1] + g_P[(size_t)ba*NH + col + 1], 0.f) * wl1;
                rs1 += fmaxf(c[mi][ni][2] + g_P[(size_t)bb*NH + col    ], 0.f) * wl0
                     + fmaxf(c[mi][ni][3] + g_P[(size_t)bb*NH + col + 1], 0.f) * wl1;
            }
            rs0 += __shfl_xor_sync(0xffffffffu, rs0, 1);
            rs0 += __shfl_xor_sync(0xffffffffu, rs0, 2);
            rs1 += __shfl_xor_sync(0xffffffffu, rs1, 1);
            rs1 += __shfl_xor_sync(0xffffffffu, rs1, 2);
            if (tig == 0){
                atomicAdd(&g_logits[row],     rs0);
                atomicAdd(&g_logits[row + 8], rs1);
            }
        }
    }
}

__global__ void __launch_bounds__(256) final_kernel(
    const float* __restrict__ mask, const float* __restrict__ bl,
    const float* __restrict__ Wse1, const float* __restrict__ Wse2,
    const float* __restrict__ Wf,   const float* __restrict__ bf,
    float* __restrict__ out)
{
    int b = blockIdx.x, tid = threadIdx.x;
    __shared__ float  s_l[KOBJ], s_s[KOBJ];
    __shared__ float4 s_wf[VD/4], s_bf[VD/4];
    for (int d = tid; d < VD/4; d += 256){
        s_wf[d] = ((const float4*)Wf)[d];
        s_bf[d] = ((const float4*)bf)[d];
    }
    if (tid < KOBJ) s_l[tid] = g_logits[b*KOBJ + tid] + bl[0];
    __syncthreads();
    if (tid < KOBJ){
        float l = s_l[tid];
        float mx = s_l[0];
        #pragma unroll
        for (int k=1;k<KOBJ;k++) mx = fmaxf(mx, s_l[k]);
        float sum = 0.f;
        #pragma unroll
        for (int k=0;k<KOBJ;k++) sum += expf(s_l[k]-mx);
        out[b*KOBJ + tid] = expf(l-mx)/sum;
        float total = 0.f;
        #pragma unroll
        for (int k=0;k<KOBJ;k++) total += s_l[k]*mask[b*KOBJ+k];
        float x = total - l*mask[b*KOBJ+tid];
        float acc = 0.f;
        for (int i=0;i<128;i++) acc += Wse2[i]*fmaxf(x*Wse1[i], 0.f);
        float y = 1.f/(1.f + expf(-acc));
        s_s[tid] = x*(1.f-y) + l;
    }
    __syncthreads();
    float* out2 = out + NROWS;
    #pragma unroll
    for (int k=0;k<KOBJ;k++){
        float s = s_s[k];
        float4* o = (float4*)(out2 + (size_t)(b*KOBJ+k)*VD);
        for (int d = tid; d < VD/4; d += 256){
            float4 wf = s_wf[d], bv = s_bf[d];
            o[d] = make_float4(fmaf(s,wf.x,bv.x), fmaf(s,wf.y,bv.y),
                               fmaf(s,wf.z,bv.z), fmaf(s,wf.w,bv.w));
        }
    }
}

extern "C" void kernel_launch(void* const* d_in, const int* in_sizes, int n_in,
                              void* d_out, int out_size)
{
    const float* v    = (const float*)d_in[0];
    const float* q    = (const float*)d_in[1];
    const float* mask = (const float*)d_in[2];
    const float* W1   = (const float*)d_in[3];
    const float* b1   = (const float*)d_in[4];
    const float* Wl   = (const float*)d_in[5];
    const float* bl   = (const float*)d_in[6];
    const float* Wse1 = (const float*)d_in[7];
    const float* Wse2 = (const float*)d_in[8];
    const float* Wf   = (const float*)d_in[9];
    const float* bf   = (const float*)d_in[10];
    float* out = (float*)d_out;

    cudaFuncSetAttribute(gemm_tc<0>, cudaFuncAttributeMaxDynamicSharedMemorySize, SMEM_DYN);
    cudaFuncSetAttribute(gemm_tc<1>, cudaFuncAttributeMaxDynamicSharedMemorySize, SMEM_DYN);

    zero_logits_kernel<<<(NROWS+255)/256, 256>>>();
    round_W1_kernel<<<(NH*LDW/4)/256, 256>>>(W1);
    // Stage A: g_P[b,h] = q[b]·W1q[h] + b1[h]
    gemm_tc<0><<<dim3(BATCH/BM, NH/BN), THREADS, SMEM_DYN>>>(q, b1, nullptr);
    // Stage B: logits[row] += Σ_h Wl[h]·relu(v[row]·W1v[h] + g_P[row/6,h])
    gemm_tc<1><<<dim3(NROWS/BM, NH/BN), THREADS, SMEM_DYN>>>(v, nullptr, Wl);
    // Stage C
    final_kernel<<<BATCH, 256>>>(mask, bl, Wse1, Wse2, Wf, bf, out);
}